// round 8
// baseline (speedup 1.0000x reference)
#include <cuda_runtime.h>
#include <cstdint>

#define NROWS 4096
#define HDIM  512
#define VDIM  32000
#define SDIM  400
#define BDIM  32
#define CDIM  620
#define OUTW  32620          // VDIM + CDIM
#define BM    128
#define BN    128
#define BK    32
#define NSTAGE (HDIM / BK)   // 16
#define NTILES (VDIM / BN)   // 250
#define STAGEF (2 * BM * BK)         // 8192 floats per stage (A+B)
#define DYNSMEM (3 * STAGEF * 4)     // 98304 bytes

__device__ float g_pcopy[NROWS];
__device__ float g_partial[NROWS * NTILES];
__device__ float g_hp[NROWS * HDIM];       // permuted hidden
__device__ float g_Wp[(size_t)VDIM * HDIM];// permuted W

// ---------------------------------------------------------------------------
__device__ __forceinline__ uint32_t smem_u32(const void* p) {
    return (uint32_t)__cvta_generic_to_shared(p);
}
__device__ __forceinline__ void cp_async16(uint32_t dst, const void* src) {
    asm volatile("cp.async.cg.shared.global [%0], [%1], 16;\n" :: "r"(dst), "l"(src));
}
__device__ __forceinline__ void cp_commit() { asm volatile("cp.async.commit_group;\n"); }
template<int N> __device__ __forceinline__ void cp_wait() {
    asm volatile("cp.async.wait_group %0;\n" :: "n"(N));
}

__device__ __forceinline__ void mma_tf32(float c[4], uint32_t a0, uint32_t a1,
                                         uint32_t a2, uint32_t a3,
                                         uint32_t b0, uint32_t b1) {
    asm volatile(
        "mma.sync.aligned.m16n8k8.row.col.f32.tf32.tf32.f32 "
        "{%0,%1,%2,%3}, {%4,%5,%6,%7}, {%8,%9}, {%0,%1,%2,%3};"
        : "+f"(c[0]), "+f"(c[1]), "+f"(c[2]), "+f"(c[3])
        : "r"(a0), "r"(a1), "r"(a2), "r"(a3), "r"(b0), "r"(b1));
}

// ---------------------------------------------------------------------------
// prep: per-row fragment permutation. Within each 16-float segment:
// phys[4t + u] = logical[4u + t]  (4x4 transpose). One float4 out per thread.
// ---------------------------------------------------------------------------
__global__ void prep_kernel(const float* __restrict__ src,
                            float* __restrict__ dst, int nf4) {
    int idx = blockIdx.x * 256 + threadIdx.x;
    if (idx >= nf4) return;
    int f   = idx << 2;                  // phys float offset
    int row = f >> 9;
    int q   = f & 511;
    int seg = q >> 4;
    int t   = (q >> 2) & 3;
    const float* s = src + (size_t)row * HDIM + seg * 16 + t;
    float4 v;
    v.x = s[0]; v.y = s[4]; v.z = s[8]; v.w = s[12];
    reinterpret_cast<float4*>(dst)[idx] = v;
}

// ---------------------------------------------------------------------------
// K1: p_copy[n] = sigmoid(hidden[n] . Wc + bc)
// ---------------------------------------------------------------------------
__global__ void pcopy_kernel(const float* __restrict__ hidden,
                             const float* __restrict__ Wc,
                             const float* __restrict__ bc) {
    int warp = (blockIdx.x * blockDim.x + threadIdx.x) >> 5;
    int lane = threadIdx.x & 31;
    if (warp >= NROWS) return;
    const float* h = hidden + (size_t)warp * HDIM;
    float s = 0.f;
    #pragma unroll
    for (int k = lane; k < HDIM; k += 32) s += h[k] * Wc[k];
    #pragma unroll
    for (int o = 16; o > 0; o >>= 1) s += __shfl_down_sync(0xffffffffu, s, o);
    if (lane == 0) g_pcopy[warp] = 1.f / (1.f + __expf(-(s + bc[0])));
}

// ---------------------------------------------------------------------------
// K2: TF32 mma.sync GEMM 128x128x512, warp tile 64x64, LDS.128 fragments,
//     3-stage cp.async, fused exp epilogue + per-tile row expsums.
// ---------------------------------------------------------------------------
__device__ __forceinline__ void load_stage(const float* __restrict__ hp,
                                           const float* __restrict__ Wp,
                                           int m0, int n0, int s,
                                           uint32_t aAddr, uint32_t bAddr, int tid) {
    const int k0 = s * BK;
    const int x = (tid & 1) << 2;
    {
        const float* sa = hp + (size_t)(m0 + tid) * HDIM + k0;
        uint32_t rb = aAddr + tid * 128;
        #pragma unroll
        for (int c = 0; c < 8; c++)
            cp_async16(rb + ((c ^ x) << 4), sa + c * 4);
    }
    {
        const float* sb = Wp + (size_t)(n0 + tid) * HDIM + k0;
        uint32_t rb = bAddr + tid * 128;
        #pragma unroll
        for (int c = 0; c < 8; c++)
            cp_async16(rb + ((c ^ x) << 4), sb + c * 4);
    }
}

__global__ __launch_bounds__(128, 2)
void gemm_kernel(const float* __restrict__ hp,
                 const float* __restrict__ Wp,
                 const float* __restrict__ bias,
                 float* __restrict__ out) {
    extern __shared__ __align__(16) float dyn[];
    __shared__ float bias_s[BN];
    __shared__ float rs_s[2][BM];

    const int tid = threadIdx.x;
    const int m0 = blockIdx.x * BM;
    const int n0 = blockIdx.y * BN;
    const int wid = tid >> 5, lane = tid & 31;
    const int wm = wid & 1;          // 2 warps along M (64 rows)
    const int wn = wid >> 1;         // 2 warps along N (64 cols)
    const int g = lane >> 2, t = lane & 3;

    if (tid < BN) bias_s[tid] = bias[n0 + tid];

    float c[4][8][4];
    #pragma unroll
    for (int mf = 0; mf < 4; mf++)
        #pragma unroll
        for (int nf = 0; nf < 8; nf++)
            #pragma unroll
            for (int i = 0; i < 4; i++) c[mf][nf][i] = 0.f;

    const uint32_t sbase = smem_u32(dyn);
    const uint32_t stA[3] = { sbase, sbase + STAGEF * 4, sbase + 2 * STAGEF * 4 };

    load_stage(hp, Wp, m0, n0, 0, stA[0], stA[0] + 16384u, tid); cp_commit();
    load_stage(hp, Wp, m0, n0, 1, stA[1], stA[1] + 16384u, tid); cp_commit();

    #pragma unroll 1
    for (int s = 0; s < NSTAGE; s++) {
        const int p = s % 3;
        if (s + 1 < NSTAGE) cp_wait<1>(); else cp_wait<0>();
        __syncthreads();

        const float* Af = dyn + p * STAGEF;
        const float* Bf = Af + BM * BK;

        #pragma unroll
        for (int jp = 0; jp < 2; jp++) {
            uint4 av[4][2], bv[8];
            #pragma unroll
            for (int mf = 0; mf < 4; mf++)
                #pragma unroll
                for (int h = 0; h < 2; h++) {
                    int row = wm * 64 + mf * 16 + h * 8 + g;
                    int ch  = (jp * 4 + t) ^ ((row & 1) << 2);
                    av[mf][h] = *reinterpret_cast<const uint4*>(Af + row * 32 + ch * 4);
                }
            #pragma unroll
            for (int nf = 0; nf < 8; nf++) {
                int row = wn * 64 + nf * 8 + g;
                int ch  = (jp * 4 + t) ^ ((row & 1) << 2);
                bv[nf] = *reinterpret_cast<const uint4*>(Bf + row * 32 + ch * 4);
            }
            #pragma unroll
            for (int mf = 0; mf < 4; mf++)
                #pragma unroll
                for (int nf = 0; nf < 8; nf++)
                    mma_tf32(c[mf][nf], av[mf][0].x, av[mf][1].x,
                             av[mf][0].y, av[mf][1].y, bv[nf].x, bv[nf].y);
            #pragma unroll
            for (int mf = 0; mf < 4; mf++)
                #pragma unroll
                for (int nf = 0; nf < 8; nf++)
                    mma_tf32(c[mf][nf], av[mf][0].z, av[mf][1].z,
                             av[mf][0].w, av[mf][1].w, bv[nf].z, bv[nf].w);
        }

        if (s + 2 < NSTAGE) {
            const int q = (s + 2) % 3;
            load_stage(hp, Wp, m0, n0, s + 2, stA[q], stA[q] + 16384u, tid);
            cp_commit();
        }
    }
    __syncthreads();

    // ---- epilogue: exp(+bias), row expsum partials, transposed f4 stores
    float rs[4][2];
    #pragma unroll
    for (int mf = 0; mf < 4; mf++) { rs[mf][0] = 0.f; rs[mf][1] = 0.f; }

    #pragma unroll
    for (int mf = 0; mf < 4; mf++)
        #pragma unroll
        for (int nf = 0; nf < 8; nf++)
            #pragma unroll
            for (int i = 0; i < 4; i++) {
                int col = wn * 64 + nf * 8 + 2 * t + (i & 1);
                float e = __expf(c[mf][nf][i] + bias_s[col]);
                c[mf][nf][i] = e;
                rs[mf][i >> 1] += e;
            }

    #pragma unroll
    for (int mf = 0; mf < 4; mf++)
        #pragma unroll
        for (int h = 0; h < 2; h++) {
            float v = rs[mf][h];
            v += __shfl_xor_sync(0xffffffffu, v, 1);
            v += __shfl_xor_sync(0xffffffffu, v, 2);
            if (t == 0) rs_s[wn][wm * 64 + mf * 16 + h * 8 + g] = v;
        }
    __syncthreads();
    if (tid < BM)
        g_partial[(size_t)(m0 + tid) * NTILES + blockIdx.y]
            = rs_s[0][tid] + rs_s[1][tid];

    #pragma unroll 1
    for (int ch = 0; ch < 4; ch++) {
        if (wn == (ch >> 1)) {
            int nfb = (ch & 1) * 4;
            #pragma unroll
            for (int mf = 0; mf < 4; mf++)
                #pragma unroll
                for (int nfo = 0; nfo < 4; nfo++)
                    #pragma unroll
                    for (int i = 0; i < 4; i++) {
                        int row = wm * 64 + mf * 16 + (i >> 1) * 8 + g;
                        int cl  = nfo * 8 + 2 * t + (i & 1);
                        dyn[cl * 132 + row] = c[mf][nfb + nfo][i];
                    }
        }
        __syncthreads();
        #pragma unroll
        for (int k = 0; k < 8; k++) {
            int f = tid + k * 128;
            int row = f >> 3, cg = f & 7;
            float4 v4;
            v4.x = dyn[(cg * 4 + 0) * 132 + row];
            v4.y = dyn[(cg * 4 + 1) * 132 + row];
            v4.z = dyn[(cg * 4 + 2) * 132 + row];
            v4.w = dyn[(cg * 4 + 3) * 132 + row];
            *reinterpret_cast<float4*>(
                &out[(size_t)(m0 + row) * OUTW + n0 + ch * 32 + cg * 4]) = v4;
        }
        __syncthreads();
    }
}

// ---------------------------------------------------------------------------
// K3: per-row reduce 250 partials (deterministic), scale V-range of out
// ---------------------------------------------------------------------------
__global__ void scale_kernel(float* __restrict__ out) {
    const int n = blockIdx.x;
    const int tid = threadIdx.x;
    __shared__ float red[256];
    red[tid] = (tid < NTILES) ? g_partial[(size_t)n * NTILES + tid] : 0.f;
    __syncthreads();
    #pragma unroll
    for (int o = 128; o > 0; o >>= 1) {
        if (tid < o) red[tid] += red[tid + o];
        __syncthreads();
    }
    const float sc = (1.f - g_pcopy[n]) / red[0];
    float4* row = reinterpret_cast<float4*>(out + (size_t)n * OUTW);
    for (int i = tid; i < VDIM / 4; i += 256) {
        float4 x = row[i];
        x.x *= sc; x.y *= sc; x.z *= sc; x.w *= sc;
        row[i] = x;
    }
}

// ---------------------------------------------------------------------------
// K4: out[n, V+c] = p_copy[n] * sum_s attn[n,s] * src_map[s,b,c],  n = t*B + b
//     8 t-rows per CTA (acc[8] -> ~50 regs -> 2 CTA/SM), unroll-8 for MLP.
// ---------------------------------------------------------------------------
__global__ void copyext_kernel(const float* __restrict__ attn,
                               const float* __restrict__ srcmap,
                               float* __restrict__ out) {
    __shared__ float a_s[8][SDIM];
    int b  = blockIdx.x & 31;
    int t0 = (blockIdx.x >> 5) << 3;

    for (int i = threadIdx.x; i < 8 * SDIM; i += blockDim.x) {
        int r = i / SDIM, s = i - r * SDIM;
        a_s[r][s] = attn[(size_t)((t0 + r) * BDIM + b) * SDIM + s];
    }
    __syncthreads();

    int c = threadIdx.x;
    if (c < CDIM) {
        float acc[8];
        #pragma unroll
        for (int r = 0; r < 8; r++) acc[r] = 0.f;
        #pragma unroll 8
        for (int s = 0; s < SDIM; s++) {
            float sv = srcmap[(size_t)(s * BDIM + b) * CDIM + c];
            #pragma unroll
            for (int r = 0; r < 8; r++) acc[r] += a_s[r][s] * sv;
        }
        #pragma unroll
        for (int r = 0; r < 8; r++) {
            int n = (t0 + r) * BDIM + b;
            out[(size_t)n * OUTW + VDIM + c] = acc[r] * g_pcopy[n];
        }
    }
}

// ---------------------------------------------------------------------------
extern "C" void kernel_launch(void* const* d_in, const int* in_sizes, int n_in,
                              void* d_out, int out_size) {
    const float* hidden = (const float*)d_in[0];   // (4096, 512)
    const float* attn   = (const float*)d_in[1];   // (4096, 400)
    const float* W      = (const float*)d_in[2];   // (32000, 512)
    const float* bias   = (const float*)d_in[3];   // (32000,)
    const float* Wc     = (const float*)d_in[4];   // (1, 512)
    const float* bc     = (const float*)d_in[5];   // (1,)
    const float* srcmap = (const float*)d_in[6];   // (400, 32, 620)
    float* out = (float*)d_out;                    // (4096, 32620)

    cudaFuncSetAttribute(gemm_kernel,
                         cudaFuncAttributeMaxDynamicSharedMemorySize, DYNSMEM);

    float* hp; cudaGetSymbolAddress((void**)&hp, g_hp);
    float* Wp; cudaGetSymbolAddress((void**)&Wp, g_Wp);

    // launch order puts gemm 4th (ncu -s 5 -c 1 lands on our 4th launch)
    pcopy_kernel<<<NROWS / 8, 256>>>(hidden, Wc, bc);
    prep_kernel<<<(NROWS * HDIM / 4 + 255) / 256, 256>>>(hidden, hp, NROWS * HDIM / 4);
    prep_kernel<<<(VDIM * HDIM / 4 + 255) / 256, 256>>>(W, Wp, VDIM * HDIM / 4);

    dim3 g2(NROWS / BM, NTILES);                   // (32, 250): M fast -> W reuse
    gemm_kernel<<<g2, 128, DYNSMEM>>>(hp, Wp, bias, out);

    copyext_kernel<<<(NROWS / BDIM / 8) * BDIM, 640>>>(attn, srcmap, out);
    scale_kernel<<<NROWS, 256>>>(out);
}

// round 9
// speedup vs baseline: 3.2175x; 3.2175x over previous
#include <cuda_runtime.h>
#include <cstdint>

#define NROWS 4096
#define HDIM  512
#define VDIM  32000
#define SDIM  400
#define BDIM  32
#define CDIM  620
#define OUTW  32620          // VDIM + CDIM
#define BM    128
#define BN    128
#define BK    32
#define NSTAGE (HDIM / BK)   // 16
#define NTILES (VDIM / BN)   // 250
#define STAGEF (2 * BM * BK)         // 8192 floats per stage (A+B)
#define DYNSMEM (3 * STAGEF * 4)     // 98304 bytes

__device__ float g_pcopy[NROWS];
__device__ float g_partial[NROWS * NTILES];
__device__ float g_hp[NROWS * HDIM];        // permuted hidden
__device__ float g_Wp[(size_t)VDIM * HDIM]; // permuted W

// ---------------------------------------------------------------------------
__device__ __forceinline__ uint32_t smem_u32(const void* p) {
    return (uint32_t)__cvta_generic_to_shared(p);
}
__device__ __forceinline__ void cp_async16(uint32_t dst, const void* src) {
    asm volatile("cp.async.cg.shared.global [%0], [%1], 16;\n" :: "r"(dst), "l"(src));
}
__device__ __forceinline__ void cp_commit() { asm volatile("cp.async.commit_group;\n"); }
template<int N> __device__ __forceinline__ void cp_wait() {
    asm volatile("cp.async.wait_group %0;\n" :: "n"(N));
}

__device__ __forceinline__ void mma_tf32(float c[4], uint32_t a0, uint32_t a1,
                                         uint32_t a2, uint32_t a3,
                                         uint32_t b0, uint32_t b1) {
    asm volatile(
        "mma.sync.aligned.m16n8k8.row.col.f32.tf32.tf32.f32 "
        "{%0,%1,%2,%3}, {%4,%5,%6,%7}, {%8,%9}, {%0,%1,%2,%3};"
        : "+f"(c[0]), "+f"(c[1]), "+f"(c[2]), "+f"(c[3])
        : "r"(a0), "r"(a1), "r"(a2), "r"(a3), "r"(b0), "r"(b1));
}

// ---------------------------------------------------------------------------
// prep: per-row fragment permutation. Within each 16-float segment:
// phys[4t + u] = logical[4u + t]  (4x4 transpose). One float4 out per thread.
// (verified correct in R7)
// ---------------------------------------------------------------------------
__global__ void prep_kernel(const float* __restrict__ src,
                            float* __restrict__ dst, int nf4) {
    int idx = blockIdx.x * 256 + threadIdx.x;
    if (idx >= nf4) return;
    int f   = idx << 2;                  // phys float offset
    int row = f >> 9;
    int q   = f & 511;
    int seg = q >> 4;
    int t   = (q >> 2) & 3;
    const float* s = src + (size_t)row * HDIM + seg * 16 + t;
    float4 v;
    v.x = s[0]; v.y = s[4]; v.z = s[8]; v.w = s[12];
    reinterpret_cast<float4*>(dst)[idx] = v;
}

// ---------------------------------------------------------------------------
// K1: p_copy[n] = sigmoid(hidden[n] . Wc + bc)
// ---------------------------------------------------------------------------
__global__ void pcopy_kernel(const float* __restrict__ hidden,
                             const float* __restrict__ Wc,
                             const float* __restrict__ bc) {
    int warp = (blockIdx.x * blockDim.x + threadIdx.x) >> 5;
    int lane = threadIdx.x & 31;
    if (warp >= NROWS) return;
    const float* h = hidden + (size_t)warp * HDIM;
    float s = 0.f;
    #pragma unroll
    for (int k = lane; k < HDIM; k += 32) s += h[k] * Wc[k];
    #pragma unroll
    for (int o = 16; o > 0; o >>= 1) s += __shfl_down_sync(0xffffffffu, s, o);
    if (lane == 0) g_pcopy[warp] = 1.f / (1.f + __expf(-(s + bc[0])));
}

// ---------------------------------------------------------------------------
// K2: TF32 mma.sync GEMM 128x128x512, warp tile 64x32, LDS.128 fragment
//     loads from permuted operands, 3-stage cp.async, fused exp epilogue.
// ---------------------------------------------------------------------------
__device__ __forceinline__ void load_stage(const float* __restrict__ hp,
                                           const float* __restrict__ Wp,
                                           int m0, int n0, int s,
                                           uint32_t aAddr, uint32_t bAddr, int tid) {
    const int k0 = s * BK;
    const int r = tid & 127;
    const bool isB = tid >= 128;
    const float* src = isB ? (Wp + (size_t)(n0 + r) * HDIM + k0)
                           : (hp + (size_t)(m0 + r) * HDIM + k0);
    uint32_t rb = (isB ? bAddr : aAddr) + (uint32_t)r * 128u;
    const int x = (r & 1) << 2;
    #pragma unroll
    for (int c = 0; c < 8; c++)
        cp_async16(rb + (uint32_t)((c ^ x) << 4), src + c * 4);
}

__global__ __launch_bounds__(256, 2)
void gemm_kernel(const float* __restrict__ hp,
                 const float* __restrict__ Wp,
                 const float* __restrict__ bias,
                 float* __restrict__ out) {
    extern __shared__ __align__(16) float dyn[];
    __shared__ float bias_s[BN];
    __shared__ float rs_s[4][BM];

    const int tid = threadIdx.x;
    const int m0 = blockIdx.x * BM;
    const int n0 = blockIdx.y * BN;
    const int wid = tid >> 5, lane = tid & 31;
    const int wm = wid & 1;          // 2 warps along M (64 rows)
    const int wn = wid >> 1;         // 4 warps along N (32 cols)
    const int g = lane >> 2, t = lane & 3;

    if (tid < BN) bias_s[tid] = bias[n0 + tid];

    float c[4][4][4];
    #pragma unroll
    for (int mf = 0; mf < 4; mf++)
        #pragma unroll
        for (int nf = 0; nf < 4; nf++)
            #pragma unroll
            for (int i = 0; i < 4; i++) c[mf][nf][i] = 0.f;

    const uint32_t sbase = smem_u32(dyn);
    const uint32_t stA[3] = { sbase, sbase + STAGEF * 4, sbase + 2 * STAGEF * 4 };

    load_stage(hp, Wp, m0, n0, 0, stA[0], stA[0] + 16384u, tid); cp_commit();
    load_stage(hp, Wp, m0, n0, 1, stA[1], stA[1] + 16384u, tid); cp_commit();

    #pragma unroll 1
    for (int s = 0; s < NSTAGE; s++) {
        const int p = s % 3;
        if (s + 1 < NSTAGE) cp_wait<1>(); else cp_wait<0>();
        __syncthreads();

        const float* Af = dyn + p * STAGEF;
        const float* Bf = Af + BM * 32;

        #pragma unroll
        for (int jp = 0; jp < 2; jp++) {          // two k16 halves of the stage
            uint4 bv[4];
            #pragma unroll
            for (int nf = 0; nf < 4; nf++) {
                int row = wn * 32 + nf * 8 + g;
                int ch  = (jp * 4 + t) ^ ((row & 1) << 2);
                bv[nf] = *reinterpret_cast<const uint4*>(Bf + row * 32 + ch * 4);
            }
            #pragma unroll
            for (int mh = 0; mh < 2; mh++) {      // mf pairs, limits live regs
                uint4 av[2][2];
                #pragma unroll
                for (int mf = 0; mf < 2; mf++)
                    #pragma unroll
                    for (int h = 0; h < 2; h++) {
                        int row = wm * 64 + (mh * 2 + mf) * 16 + h * 8 + g;
                        int ch  = (jp * 4 + t) ^ ((row & 1) << 2);
                        av[mf][h] = *reinterpret_cast<const uint4*>(Af + row * 32 + ch * 4);
                    }
                #pragma unroll
                for (int mf = 0; mf < 2; mf++)
                    #pragma unroll
                    for (int nf = 0; nf < 4; nf++) {
                        mma_tf32(c[mh * 2 + mf][nf],
                                 av[mf][0].x, av[mf][1].x, av[mf][0].y, av[mf][1].y,
                                 bv[nf].x, bv[nf].y);
                        mma_tf32(c[mh * 2 + mf][nf],
                                 av[mf][0].z, av[mf][1].z, av[mf][0].w, av[mf][1].w,
                                 bv[nf].z, bv[nf].w);
                    }
            }
        }

        if (s + 2 < NSTAGE) {
            const int q = (s + 2) % 3;
            load_stage(hp, Wp, m0, n0, s + 2, stA[q], stA[q] + 16384u, tid);
            cp_commit();
        }
    }
    __syncthreads();

    // ---- epilogue: exp(+bias), row-sum partials, transposed coalesced stores
    float rs[4][2];
    #pragma unroll
    for (int mf = 0; mf < 4; mf++) { rs[mf][0] = 0.f; rs[mf][1] = 0.f; }

    #pragma unroll
    for (int mf = 0; mf < 4; mf++)
        #pragma unroll
        for (int nf = 0; nf < 4; nf++)
            #pragma unroll
            for (int i = 0; i < 4; i++) {
                int col = wn * 32 + nf * 8 + 2 * t + (i & 1);
                float e = __expf(c[mf][nf][i] + bias_s[col]);
                c[mf][nf][i] = e;
                rs[mf][i >> 1] += e;
            }

    #pragma unroll
    for (int mf = 0; mf < 4; mf++)
        #pragma unroll
        for (int h = 0; h < 2; h++) {
            float v = rs[mf][h];
            v += __shfl_xor_sync(0xffffffffu, v, 1);
            v += __shfl_xor_sync(0xffffffffu, v, 2);
            if (t == 0) rs_s[wn][wm * 64 + mf * 16 + g + h * 8] = v;
        }
    __syncthreads();
    if (tid < BM) {
        float pr = rs_s[0][tid] + rs_s[1][tid] + rs_s[2][tid] + rs_s[3][tid];
        g_partial[(size_t)(m0 + tid) * NTILES + blockIdx.y] = pr;
    }

    // 4 chunks of 32 cols: STS (conflict-free, stride 132) then float4 STG
    #pragma unroll 1
    for (int ch = 0; ch < 4; ch++) {
        if (wn == ch) {
            #pragma unroll
            for (int mf = 0; mf < 4; mf++)
                #pragma unroll
                for (int nf = 0; nf < 4; nf++)
                    #pragma unroll
                    for (int i = 0; i < 4; i++) {
                        int row = wm * 64 + mf * 16 + g + (i >> 1) * 8;
                        int col = nf * 8 + 2 * t + (i & 1);
                        dyn[col * 132 + row] = c[mf][nf][i];
                    }
        }
        __syncthreads();
        #pragma unroll
        for (int k = 0; k < 4; k++) {
            int f = tid + k * 256;
            int row = f >> 3, cg = f & 7;
            float4 v4;
            v4.x = dyn[(cg * 4 + 0) * 132 + row];
            v4.y = dyn[(cg * 4 + 1) * 132 + row];
            v4.z = dyn[(cg * 4 + 2) * 132 + row];
            v4.w = dyn[(cg * 4 + 3) * 132 + row];
            *reinterpret_cast<float4*>(
                &out[(size_t)(m0 + row) * OUTW + n0 + ch * 32 + cg * 4]) = v4;
        }
        __syncthreads();
    }
}

// ---------------------------------------------------------------------------
// K3: per-row reduce 250 partials (deterministic), scale V-range of out
// ---------------------------------------------------------------------------
__global__ void scale_kernel(float* __restrict__ out) {
    const int n = blockIdx.x;
    const int tid = threadIdx.x;
    __shared__ float red[256];
    red[tid] = (tid < NTILES) ? g_partial[(size_t)n * NTILES + tid] : 0.f;
    __syncthreads();
    #pragma unroll
    for (int o = 128; o > 0; o >>= 1) {
        if (tid < o) red[tid] += red[tid + o];
        __syncthreads();
    }
    const float sc = (1.f - g_pcopy[n]) / red[0];
    float4* row = reinterpret_cast<float4*>(out + (size_t)n * OUTW);
    for (int i = tid; i < VDIM / 4; i += 256) {
        float4 x = row[i];
        x.x *= sc; x.y *= sc; x.z *= sc; x.w *= sc;
        row[i] = x;
    }
}

// ---------------------------------------------------------------------------
// K4: out[n, V+c] = p_copy[n] * sum_s attn[n,s] * src_map[s,b,c],  n = t*B + b
//     8 t-rows per CTA (acc[8] -> ~50 regs -> 2 CTA/SM), unroll-8 for MLP.
// ---------------------------------------------------------------------------
__global__ void copyext_kernel(const float* __restrict__ attn,
                               const float* __restrict__ srcmap,
                               float* __restrict__ out) {
    __shared__ float a_s[8][SDIM];
    int b  = blockIdx.x & 31;
    int t0 = (blockIdx.x >> 5) << 3;

    for (int i = threadIdx.x; i < 8 * SDIM; i += blockDim.x) {
        int r = i / SDIM, s = i - r * SDIM;
        a_s[r][s] = attn[(size_t)((t0 + r) * BDIM + b) * SDIM + s];
    }
    __syncthreads();

    int c = threadIdx.x;
    if (c < CDIM) {
        float acc[8];
        #pragma unroll
        for (int r = 0; r < 8; r++) acc[r] = 0.f;
        #pragma unroll 8
        for (int s = 0; s < SDIM; s++) {
            float sv = srcmap[(size_t)(s * BDIM + b) * CDIM + c];
            #pragma unroll
            for (int r = 0; r < 8; r++) acc[r] += a_s[r][s] * sv;
        }
        #pragma unroll
        for (int r = 0; r < 8; r++) {
            int n = (t0 + r) * BDIM + b;
            out[(size_t)n * OUTW + VDIM + c] = acc[r] * g_pcopy[n];
        }
    }
}

// ---------------------------------------------------------------------------
extern "C" void kernel_launch(void* const* d_in, const int* in_sizes, int n_in,
                              void* d_out, int out_size) {
    const float* hidden = (const float*)d_in[0];   // (4096, 512)
    const float* attn   = (const float*)d_in[1];   // (4096, 400)
    const float* W      = (const float*)d_in[2];   // (32000, 512)
    const float* bias   = (const float*)d_in[3];   // (32000,)
    const float* Wc     = (const float*)d_in[4];   // (1, 512)
    const float* bc     = (const float*)d_in[5];   // (1,)
    const float* srcmap = (const float*)d_in[6];   // (400, 32, 620)
    float* out = (float*)d_out;                    // (4096, 32620)

    cudaFuncSetAttribute(gemm_kernel,
                         cudaFuncAttributeMaxDynamicSharedMemorySize, DYNSMEM);

    float* hp; cudaGetSymbolAddress((void**)&hp, g_hp);
    float* Wp; cudaGetSymbolAddress((void**)&Wp, g_Wp);

    // launch order keeps gemm 4th (ncu -s 5 -c 1 lands on our 4th launch)
    pcopy_kernel<<<NROWS / 8, 256>>>(hidden, Wc, bc);
    prep_kernel<<<(NROWS * HDIM / 4 + 255) / 256, 256>>>(hidden, hp, NROWS * HDIM / 4);
    prep_kernel<<<(VDIM * HDIM / 4 + 255) / 256, 256>>>(W, Wp, VDIM * HDIM / 4);

    dim3 g2(NROWS / BM, NTILES);                   // (32, 250): M fast -> W reuse
    gemm_kernel<<<g2, 256, DYNSMEM>>>(hp, Wp, bias, out);

    copyext_kernel<<<(NROWS / BDIM / 8) * BDIM, 640>>>(attn, srcmap, out);
    scale_kernel<<<NROWS, 256>>>(out);
}